// round 7
// baseline (speedup 1.0000x reference)
#include <cuda_runtime.h>
#include <cuda_bf16.h>

// SparseVoxelEncoder: trilinear interpolation of 8 corner embeddings per point.
// P = 1048576 points, H = 524288 voxels, NEMB = 600000 embeddings, D = 32.
//
// R2-R5 established: kernel sits at the L2/DRAM traffic wall (~1.15GB LTS,
// ~500MB DRAM); cache-policy hints are neutral. R6 reduces the traffic itself:
// counting-sort points by voxel id so the ~2.2 points sharing a voxel become
// adjacent 8-lane groups in the SAME warp -> their corner-row LDGs hit the
// same 128B lines and L1tex merges them. Gather L2 traffic ~1.0GB -> ~0.5GB.
//
// Pipeline (one graph, 7 kernels): zero counts -> histogram -> 2-level
// exclusive scan -> scatter perm -> main (permuted trilerp).
// Scatter order within a voxel is atomic-nondeterministic, but each point's
// result is computed identically regardless of slot -> output deterministic.

#define P_TOTAL   1048576
#define H_TOTAL   524288
#define SCAN_TPB  1024
#define SCAN_BLK  (H_TOTAL / SCAN_TPB)   // 512
#define NTHREADS  256

__device__ int g_cnt[H_TOTAL];     // counts -> excl-in-block -> cursor
__device__ int g_bsums[SCAN_BLK];  // per-block sums -> exclusive block bases
__device__ int g_perm[P_TOTAL];    // sorted-order -> original point id

// ---------------- pass 1: zero counters ----------------
__global__ void k_zero()
{
    int i = blockIdx.x * blockDim.x + threadIdx.x;
    if (i < H_TOTAL) g_cnt[i] = 0;
}

// ---------------- pass 2: histogram of voxel ids ----------------
__global__ void k_hist(const int* __restrict__ sampled_idx)
{
    int i = blockIdx.x * blockDim.x + threadIdx.x;
    if (i < P_TOTAL) atomicAdd(&g_cnt[__ldcs(&sampled_idx[i])], 1);
}

// ---------------- pass 3a: per-block inclusive scan ----------------
__global__ __launch_bounds__(SCAN_TPB)
void k_scan1()
{
    __shared__ int sh[SCAN_TPB];
    const int t = threadIdx.x;
    const int i = blockIdx.x * SCAN_TPB + t;
    const int v = g_cnt[i];
    sh[t] = v;
    __syncthreads();
#pragma unroll
    for (int ofs = 1; ofs < SCAN_TPB; ofs <<= 1) {
        int a = (t >= ofs) ? sh[t - ofs] : 0;
        __syncthreads();
        sh[t] += a;
        __syncthreads();
    }
    g_cnt[i] = sh[t] - v;                       // exclusive within block
    if (t == SCAN_TPB - 1) g_bsums[blockIdx.x] = sh[t];
}

// ---------------- pass 3b: scan the 512 block sums ----------------
__global__ __launch_bounds__(SCAN_BLK)
void k_scan2()
{
    __shared__ int sh[SCAN_BLK];
    const int t = threadIdx.x;
    const int v = g_bsums[t];
    sh[t] = v;
    __syncthreads();
#pragma unroll
    for (int ofs = 1; ofs < SCAN_BLK; ofs <<= 1) {
        int a = (t >= ofs) ? sh[t - ofs] : 0;
        __syncthreads();
        sh[t] += a;
        __syncthreads();
    }
    g_bsums[t] = sh[t] - v;                     // exclusive block base
}

// ---------------- pass 3c: add block bases -> global cursor ----------------
__global__ void k_scan3()
{
    int i = blockIdx.x * blockDim.x + threadIdx.x;
    if (i < H_TOTAL) g_cnt[i] += g_bsums[i >> 10];   // g_cnt = exclusive base
}

// ---------------- pass 4: scatter sorted permutation ----------------
__global__ void k_scatter(const int* __restrict__ sampled_idx)
{
    int i = blockIdx.x * blockDim.x + threadIdx.x;
    if (i < P_TOTAL) {
        int h   = __ldcs(&sampled_idx[i]);
        int pos = atomicAdd(&g_cnt[h], 1);
        g_perm[pos] = i;
    }
}

// ---------------- pass 5: trilerp over voxel-sorted points ----------------
__global__ __launch_bounds__(NTHREADS)
void sve_trilerp_sorted(const float* __restrict__ sampled_xyz,   // [P,3]
                        const float* __restrict__ point_xyz,     // [H,3]
                        const float* __restrict__ values,        // [NEMB,32]
                        const int*  __restrict__ sampled_idx,    // [P] int32
                        const int*  __restrict__ point_feats,    // [H,8] int32
                        float* __restrict__ out)                 // [P,32]
{
    const int tid   = blockIdx.x * NTHREADS + threadIdx.x;
    const int slot  = tid >> 3;        // sorted position, 8 lanes per point
    const int c     = tid & 7;         // this lane's corner id (0..7)
    const int gbase = threadIdx.x & 24;// group base lane within warp

    const int p = __ldg(&g_perm[slot]);       // original point id
    const int h = __ldg(&sampled_idx[p]);     // voxel id (sorted: runs of equal h)

    const float sx = __ldg(&sampled_xyz[3 * p + 0]);
    const float sy = __ldg(&sampled_xyz[3 * p + 1]);
    const float sz = __ldg(&sampled_xyz[3 * p + 2]);
    const float px = __ldg(&point_xyz[3 * h + 0]);
    const float py = __ldg(&point_xyz[3 * h + 1]);
    const float pz = __ldg(&point_xyz[3 * h + 2]);

    // normalized position inside voxel, in [0,1]^3 (1/VOXEL_SIZE = 4)
    const float p0 = (sx - px) * 4.0f + 0.5f;
    const float p1 = (sy - py) * 4.0f + 0.5f;
    const float p2 = (sz - pz) * 4.0f + 0.5f;

    // corner q = (c>>2, (c>>1)&1, c&1); weight per dim = q ? p : (1-p)
    const float wx = (c & 4) ? p0 : 1.0f - p0;
    const float wy = (c & 2) ? p1 : 1.0f - p1;
    const float wz = (c & 1) ? p2 : 1.0f - p2;
    const float w  = wx * wy * wz;

    const int e = __ldg(&point_feats[(size_t)h * 8 + c]);

    // broadcast (e, w) of all 8 corners within the group
    int   ek[8];
    float wk[8];
#pragma unroll
    for (int k = 0; k < 8; ++k) {
        ek[k] = __shfl_sync(0xffffffffu, e, gbase + k);
        wk[k] = __shfl_sync(0xffffffffu, w, gbase + k);
    }

    // gather: lane c reads float4 slice [4c..4c+3] of each corner row.
    // Adjacent groups in this warp mostly share h -> same 128B lines ->
    // L1tex merges the duplicate line fetches within each LDG wavefront.
    const float4* __restrict__ vrows = (const float4*)values; // row = 8 float4
    float4 f[8];
#pragma unroll
    for (int k = 0; k < 8; ++k)
        f[k] = __ldg(&vrows[(size_t)ek[k] * 8 + c]);

    float4 acc = make_float4(0.f, 0.f, 0.f, 0.f);
#pragma unroll
    for (int k = 0; k < 8; ++k) {
        acc.x = fmaf(wk[k], f[k].x, acc.x);
        acc.y = fmaf(wk[k], f[k].y, acc.y);
        acc.z = fmaf(wk[k], f[k].z, acc.z);
        acc.w = fmaf(wk[k], f[k].w, acc.w);
    }

    // write-once output: streaming store, rows land at original point order
    __stcs(&((float4*)out)[(size_t)p * 8 + c], acc);
}

extern "C" void kernel_launch(void* const* d_in, const int* in_sizes, int n_in,
                              void* d_out, int out_size)
{
    const float* sampled_xyz = (const float*)d_in[0];
    const float* point_xyz   = (const float*)d_in[1];
    const float* values      = (const float*)d_in[2];
    const int*   sampled_idx = (const int*)d_in[3];
    const int*   point_feats = (const int*)d_in[4];
    float*       out         = (float*)d_out;

    k_zero   <<<H_TOTAL / 1024, 1024>>>();
    k_hist   <<<P_TOTAL / 256, 256>>>(sampled_idx);
    k_scan1  <<<SCAN_BLK, SCAN_TPB>>>();
    k_scan2  <<<1, SCAN_BLK>>>();
    k_scan3  <<<H_TOTAL / 1024, 1024>>>();
    k_scatter<<<P_TOTAL / 256, 256>>>(sampled_idx);

    sve_trilerp_sorted<<<(P_TOTAL * 8) / NTHREADS, NTHREADS>>>(
        sampled_xyz, point_xyz, values, sampled_idx, point_feats, out);
}

// round 10
// speedup vs baseline: 1.3688x; 1.3688x over previous
#include <cuda_runtime.h>
#include <cuda_fp16.h>
#include <cuda_bf16.h>

// SparseVoxelEncoder: trilinear interpolation of 8 corner embeddings per point.
// P = 1048576 points, H = 524288 voxels, NEMB = 600000 embeddings, D = 32.
//
// R2-R5: direct fp32 kernel pinned at ~1.15GB LTS / ~500MB DRAM (values-table
// refills; 77MB fp32 table can't stay L2-resident). R6 sort regressed.
// R7/R9: per-launch fp32->fp16 conversion of the table into a static
// __device__ buffer. Gather bytes halve (1.0GB -> 0.5GB), table shrinks to
// 38.4MB and stays L2-resident (conversion stores pre-populate L2), so values
// DRAM refills ~vanish. Weights stay fp32; fp16 quantization ~1.4e-4 RMS
// relative error, well under the 1e-3 threshold.
// (R8 compile fix: store __half2 directly instead of fabricated intrinsic.)

#define P_TOTAL   1048576
#define NEMB      600000
#define D_DIM     32
#define NTHREADS  256

__device__ __align__(16) __half g_vals_h[(size_t)NEMB * D_DIM];  // 38.4 MB

// ---------------- pass 1: fp32 -> fp16 table conversion ----------------
__global__ __launch_bounds__(256)
void k_convert(const float* __restrict__ values)
{
    // 19.2M elems, float4 granularity: 4.8M float4s -> 4.8M half2-pairs
    const int n4 = NEMB * D_DIM / 4;
    __half2* __restrict__ dst = (__half2*)g_vals_h;
    for (int i = blockIdx.x * 256 + threadIdx.x; i < n4; i += gridDim.x * 256) {
        float4 v = __ldcs(&((const float4*)values)[i]);   // stream, don't pollute L2
        dst[2 * i + 0] = __floats2half2_rn(v.x, v.y);
        dst[2 * i + 1] = __floats2half2_rn(v.z, v.w);
    }
}

// ---------------- pass 2: trilerp with fp16 gathers ----------------
__global__ __launch_bounds__(NTHREADS)
void sve_trilerp_kernel(const float* __restrict__ sampled_xyz,   // [P,3]
                        const float* __restrict__ point_xyz,     // [H,3]
                        const int*  __restrict__ sampled_idx,    // [P] int32
                        const int*  __restrict__ point_feats,    // [H,8] int32
                        float* __restrict__ out)                 // [P,32]
{
    const int tid   = blockIdx.x * NTHREADS + threadIdx.x;
    const int point = tid >> 3;        // 8 lanes per point
    const int c     = tid & 7;         // this lane's corner id (0..7)
    const int gbase = threadIdx.x & 24;// group base lane within warp

    // ---- per-point scalars ----
    const int h = __ldcs(&sampled_idx[point]);

    const float sx = __ldcs(&sampled_xyz[3 * point + 0]);
    const float sy = __ldcs(&sampled_xyz[3 * point + 1]);
    const float sz = __ldcs(&sampled_xyz[3 * point + 2]);
    const float px = __ldg(&point_xyz[3 * h + 0]);
    const float py = __ldg(&point_xyz[3 * h + 1]);
    const float pz = __ldg(&point_xyz[3 * h + 2]);

    // normalized position inside voxel, in [0,1]^3 (1/VOXEL_SIZE = 4)
    const float p0 = (sx - px) * 4.0f + 0.5f;
    const float p1 = (sy - py) * 4.0f + 0.5f;
    const float p2 = (sz - pz) * 4.0f + 0.5f;

    // corner q = (c>>2, (c>>1)&1, c&1); weight per dim = q ? p : (1-p)
    const float wx = (c & 4) ? p0 : 1.0f - p0;
    const float wy = (c & 2) ? p1 : 1.0f - p1;
    const float wz = (c & 1) ? p2 : 1.0f - p2;
    const float w  = wx * wy * wz;

    // this lane's corner embedding id
    const int e = __ldg(&point_feats[(size_t)h * 8 + c]);

    // ---- broadcast (e, w) of all 8 corners within the group ----
    int   ek[8];
    float wk[8];
#pragma unroll
    for (int k = 0; k < 8; ++k) {
        ek[k] = __shfl_sync(0xffffffffu, e, gbase + k);
        wk[k] = __shfl_sync(0xffffffffu, w, gbase + k);
    }

    // ---- gather: lane c reads 4 halves (dims 4c..4c+3) of each corner row ----
    // half row = 64B; 8 lanes x 8B = full row, zero waste. Table is
    // 38.4MB -> L2-resident, so these are ~all L2 hits.
    const uint2* __restrict__ vrows = (const uint2*)g_vals_h; // row = 8 uint2
    uint2 f[8];
#pragma unroll
    for (int k = 0; k < 8; ++k)
        f[k] = __ldg(&vrows[(size_t)ek[k] * 8 + c]);

    float4 acc = make_float4(0.f, 0.f, 0.f, 0.f);
#pragma unroll
    for (int k = 0; k < 8; ++k) {
        const __half2 h01 = *(const __half2*)&f[k].x;
        const __half2 h23 = *(const __half2*)&f[k].y;
        const float2 a = __half22float2(h01);
        const float2 b = __half22float2(h23);
        acc.x = fmaf(wk[k], a.x, acc.x);
        acc.y = fmaf(wk[k], a.y, acc.y);
        acc.z = fmaf(wk[k], b.x, acc.z);
        acc.w = fmaf(wk[k], b.y, acc.w);
    }

    // write-once output: streaming store (keep L2 for the half table)
    __stcs(&((float4*)out)[(size_t)point * 8 + c], acc);
}

extern "C" void kernel_launch(void* const* d_in, const int* in_sizes, int n_in,
                              void* d_out, int out_size)
{
    const float* sampled_xyz = (const float*)d_in[0];
    const float* point_xyz   = (const float*)d_in[1];
    const float* values      = (const float*)d_in[2];
    const int*   sampled_idx = (const int*)d_in[3];
    const int*   point_feats = (const int*)d_in[4];
    float*       out         = (float*)d_out;

    k_convert<<<4096, 256>>>(values);

    sve_trilerp_kernel<<<(P_TOTAL * 8) / NTHREADS, NTHREADS>>>(
        sampled_xyz, point_xyz, sampled_idx, point_feats, out);
}

// round 11
// speedup vs baseline: 1.3968x; 1.0204x over previous
#include <cuda_runtime.h>
#include <cuda_fp16.h>
#include <cuda_bf16.h>

// SparseVoxelEncoder: trilinear interpolation of 8 corner embeddings per point.
// P = 1048576 points, H = 524288 voxels, NEMB = 600000 embeddings, D = 32.
//
// R9 (94.3us = convert 15.7 + main 78.6): fp16 shadow table killed the DRAM
// wall (39.6%); main kernel now L1tex-bound (73.9%) with issue 51.5%.
// R10: 4 lanes per point, LDG.128 gathers (16B slice per corner per lane).
// Warp covers 8 points -> warp count, shfl count, and issue pressure halve;
// gather bytes and L1 wavefronts unchanged. Output via 2x STG.128 per lane.

#define P_TOTAL   1048576
#define NEMB      600000
#define D_DIM     32
#define NTHREADS  256

__device__ __align__(16) __half g_vals_h[(size_t)NEMB * D_DIM];  // 38.4 MB

// ---------------- pass 1: fp32 -> fp16 table conversion ----------------
__global__ __launch_bounds__(256)
void k_convert(const float* __restrict__ values)
{
    const int n4 = NEMB * D_DIM / 4;   // 4.8M float4s
    __half2* __restrict__ dst = (__half2*)g_vals_h;
    for (int i = blockIdx.x * 256 + threadIdx.x; i < n4; i += gridDim.x * 256) {
        float4 v = __ldcs(&((const float4*)values)[i]);   // stream reads
        dst[2 * i + 0] = __floats2half2_rn(v.x, v.y);
        dst[2 * i + 1] = __floats2half2_rn(v.z, v.w);     // default writes -> L2
    }
}

// ---------------- pass 2: trilerp, 4 lanes per point ----------------
__global__ __launch_bounds__(NTHREADS)
void sve_trilerp_kernel(const float* __restrict__ sampled_xyz,   // [P,3]
                        const float* __restrict__ point_xyz,     // [H,3]
                        const int*  __restrict__ sampled_idx,    // [P] int32
                        const int*  __restrict__ point_feats,    // [H,8] int32
                        float* __restrict__ out)                 // [P,32]
{
    const int tid   = blockIdx.x * NTHREADS + threadIdx.x;
    const int point = tid >> 2;          // 4 lanes per point
    const int c4    = tid & 3;           // lane's quarter index (0..3)
    const int gbase = threadIdx.x & 28;  // group base lane within warp

    // ---- per-point scalars ----
    const int h = __ldcs(&sampled_idx[point]);

    const float sx = __ldcs(&sampled_xyz[3 * point + 0]);
    const float sy = __ldcs(&sampled_xyz[3 * point + 1]);
    const float sz = __ldcs(&sampled_xyz[3 * point + 2]);
    const float px = __ldg(&point_xyz[3 * h + 0]);
    const float py = __ldg(&point_xyz[3 * h + 1]);
    const float pz = __ldg(&point_xyz[3 * h + 2]);

    // normalized position inside voxel, in [0,1]^3 (1/VOXEL_SIZE = 4)
    const float p0 = (sx - px) * 4.0f + 0.5f;
    const float p1 = (sy - py) * 4.0f + 0.5f;
    const float p2 = (sz - pz) * 4.0f + 0.5f;

    // lane c4 owns corners k0=2*c4 (z=0) and k0+1 (z=1).
    // corner bits: x = k&4, y = k&2, z = k&1
    const float wx = (c4 & 2) ? p0 : 1.0f - p0;
    const float wy = (c4 & 1) ? p1 : 1.0f - p1;
    const float wxy = wx * wy;
    const float w0 = wxy * (1.0f - p2);
    const float w1 = wxy * p2;

    // corner embedding ids (2 per lane, one int2)
    const int2 e01 = __ldg(&((const int2*)point_feats)[(size_t)h * 4 + c4]);
    const int e0 = e01.x, e1 = e01.y;

    // ---- broadcast (e, w) of all 8 corners within the 4-lane group ----
    int   ek[8];
    float wk[8];
#pragma unroll
    for (int j = 0; j < 4; ++j) {
        ek[2 * j + 0] = __shfl_sync(0xffffffffu, e0, gbase + j);
        ek[2 * j + 1] = __shfl_sync(0xffffffffu, e1, gbase + j);
        wk[2 * j + 0] = __shfl_sync(0xffffffffu, w0, gbase + j);
        wk[2 * j + 1] = __shfl_sync(0xffffffffu, w1, gbase + j);
    }

    // ---- gather: lane c4 reads 16B (8 halves, dims 8c4..8c4+7) per corner ----
    const uint4* __restrict__ vrows = (const uint4*)g_vals_h; // row = 4 uint4
    uint4 f[8];
#pragma unroll
    for (int k = 0; k < 8; ++k)
        f[k] = __ldg(&vrows[(size_t)ek[k] * 4 + c4]);

    float acc[8];
#pragma unroll
    for (int d = 0; d < 8; ++d) acc[d] = 0.0f;

#pragma unroll
    for (int k = 0; k < 8; ++k) {
        const float w = wk[k];
        const float2 a = __half22float2(*(const __half2*)&f[k].x);
        const float2 b = __half22float2(*(const __half2*)&f[k].y);
        const float2 cc = __half22float2(*(const __half2*)&f[k].z);
        const float2 dd = __half22float2(*(const __half2*)&f[k].w);
        acc[0] = fmaf(w, a.x, acc[0]);
        acc[1] = fmaf(w, a.y, acc[1]);
        acc[2] = fmaf(w, b.x, acc[2]);
        acc[3] = fmaf(w, b.y, acc[3]);
        acc[4] = fmaf(w, cc.x, acc[4]);
        acc[5] = fmaf(w, cc.y, acc[5]);
        acc[6] = fmaf(w, dd.x, acc[6]);
        acc[7] = fmaf(w, dd.y, acc[7]);
    }

    // write-once output: 2x streaming STG.128, coalesced
    float4* orow = (float4*)out + (size_t)point * 8 + c4 * 2;
    __stcs(&orow[0], make_float4(acc[0], acc[1], acc[2], acc[3]));
    __stcs(&orow[1], make_float4(acc[4], acc[5], acc[6], acc[7]));
}

extern "C" void kernel_launch(void* const* d_in, const int* in_sizes, int n_in,
                              void* d_out, int out_size)
{
    const float* sampled_xyz = (const float*)d_in[0];
    const float* point_xyz   = (const float*)d_in[1];
    const float* values      = (const float*)d_in[2];
    const int*   sampled_idx = (const int*)d_in[3];
    const int*   point_feats = (const int*)d_in[4];
    float*       out         = (float*)d_out;

    k_convert<<<4096, 256>>>(values);

    sve_trilerp_kernel<<<(P_TOTAL * 4) / NTHREADS, NTHREADS>>>(
        sampled_xyz, point_xyz, sampled_idx, point_feats, out);
}

// round 12
// speedup vs baseline: 1.4075x; 1.0077x over previous
#include <cuda_runtime.h>
#include <cuda_fp16.h>
#include <cuda_bf16.h>

// SparseVoxelEncoder: trilinear interpolation of 8 corner embeddings per point.
// P = 1048576 points, H = 524288 voxels, NEMB = 600000 embeddings, D = 32.
//
// R9: fp16 shadow table (convert ~15.5us) -> main kernel DRAM-unbound.
// R10: 4 lanes/point + LDG.128 gathers; main 77.2us, L1tex 68.6% = binding
// (wavefront model: ~116 wf/warp, gather floor 64).
// R11: cut non-gather wavefronts. point_xyz: lane-split component load
// (1 LDG x 8 lines instead of 3 x 8) + shfl broadcast of the normalized
// coordinate. Same for sampled_xyz (3 wf -> 1). ~116 -> ~94 wf/warp.

#define P_TOTAL   1048576
#define NEMB      600000
#define D_DIM     32
#define NTHREADS  256

__device__ __align__(16) __half g_vals_h[(size_t)NEMB * D_DIM];  // 38.4 MB

// ---------------- pass 1: fp32 -> fp16 table conversion ----------------
__global__ __launch_bounds__(256)
void k_convert(const float* __restrict__ values)
{
    const int n4 = NEMB * D_DIM / 4;   // 4.8M float4s
    __half2* __restrict__ dst = (__half2*)g_vals_h;
    for (int i = blockIdx.x * 256 + threadIdx.x; i < n4; i += gridDim.x * 256) {
        float4 v = __ldcs(&((const float4*)values)[i]);   // stream reads
        dst[2 * i + 0] = __floats2half2_rn(v.x, v.y);
        dst[2 * i + 1] = __floats2half2_rn(v.z, v.w);     // default writes -> L2
    }
}

// ---------------- pass 2: trilerp, 4 lanes per point ----------------
__global__ __launch_bounds__(NTHREADS)
void sve_trilerp_kernel(const float* __restrict__ sampled_xyz,   // [P,3]
                        const float* __restrict__ point_xyz,     // [H,3]
                        const int*  __restrict__ sampled_idx,    // [P] int32
                        const int*  __restrict__ point_feats,    // [H,8] int32
                        float* __restrict__ out)                 // [P,32]
{
    const int tid   = blockIdx.x * NTHREADS + threadIdx.x;
    const int point = tid >> 2;          // 4 lanes per point
    const int c4    = tid & 3;           // lane's quarter index (0..3)
    const int gbase = threadIdx.x & 28;  // group base lane within warp

    // ---- per-point scalars ----
    const int h = __ldcs(&sampled_idx[point]);   // same addr across group

    // lane-split coordinate load: lane c4 loads component min(c4,2).
    // One LDG each instead of 3 -> 8 wavefronts instead of 24 (point_xyz),
    // 1 instead of 3 (sampled_xyz).
    const int comp = (c4 < 3) ? c4 : 2;
    const float sv = __ldcs(&sampled_xyz[3 * point + comp]);
    const float pv = __ldg(&point_xyz[3 * h + comp]);
    // normalized coordinate for this lane's component (1/VOXEL_SIZE = 4)
    const float pc = (sv - pv) * 4.0f + 0.5f;

    // broadcast the 3 normalized coords across the 4-lane group
    const float p0 = __shfl_sync(0xffffffffu, pc, gbase + 0);
    const float p1 = __shfl_sync(0xffffffffu, pc, gbase + 1);
    const float p2 = __shfl_sync(0xffffffffu, pc, gbase + 2);

    // lane c4 owns corners k0=2*c4 (z=0) and k0+1 (z=1).
    // corner bits: x = k&4, y = k&2, z = k&1
    const float wx = (c4 & 2) ? p0 : 1.0f - p0;
    const float wy = (c4 & 1) ? p1 : 1.0f - p1;
    const float wxy = wx * wy;
    const float w0 = wxy * (1.0f - p2);
    const float w1 = wxy * p2;

    // corner embedding ids (2 per lane, one int2)
    const int2 e01 = __ldg(&((const int2*)point_feats)[(size_t)h * 4 + c4]);
    const int e0 = e01.x, e1 = e01.y;

    // ---- broadcast (e, w) of all 8 corners within the 4-lane group ----
    int   ek[8];
    float wk[8];
#pragma unroll
    for (int j = 0; j < 4; ++j) {
        ek[2 * j + 0] = __shfl_sync(0xffffffffu, e0, gbase + j);
        ek[2 * j + 1] = __shfl_sync(0xffffffffu, e1, gbase + j);
        wk[2 * j + 0] = __shfl_sync(0xffffffffu, w0, gbase + j);
        wk[2 * j + 1] = __shfl_sync(0xffffffffu, w1, gbase + j);
    }

    // ---- gather: lane c4 reads 16B (8 halves, dims 8c4..8c4+7) per corner ----
    const uint4* __restrict__ vrows = (const uint4*)g_vals_h; // row = 4 uint4
    uint4 f[8];
#pragma unroll
    for (int k = 0; k < 8; ++k)
        f[k] = __ldg(&vrows[(size_t)ek[k] * 4 + c4]);

    float acc[8];
#pragma unroll
    for (int d = 0; d < 8; ++d) acc[d] = 0.0f;

#pragma unroll
    for (int k = 0; k < 8; ++k) {
        const float w = wk[k];
        const float2 a = __half22float2(*(const __half2*)&f[k].x);
        const float2 b = __half22float2(*(const __half2*)&f[k].y);
        const float2 cc = __half22float2(*(const __half2*)&f[k].z);
        const float2 dd = __half22float2(*(const __half2*)&f[k].w);
        acc[0] = fmaf(w, a.x, acc[0]);
        acc[1] = fmaf(w, a.y, acc[1]);
        acc[2] = fmaf(w, b.x, acc[2]);
        acc[3] = fmaf(w, b.y, acc[3]);
        acc[4] = fmaf(w, cc.x, acc[4]);
        acc[5] = fmaf(w, cc.y, acc[5]);
        acc[6] = fmaf(w, dd.x, acc[6]);
        acc[7] = fmaf(w, dd.y, acc[7]);
    }

    // write-once output: 2x streaming STG.128
    float4* orow = (float4*)out + (size_t)point * 8 + c4 * 2;
    __stcs(&orow[0], make_float4(acc[0], acc[1], acc[2], acc[3]));
    __stcs(&orow[1], make_float4(acc[4], acc[5], acc[6], acc[7]));
}

extern "C" void kernel_launch(void* const* d_in, const int* in_sizes, int n_in,
                              void* d_out, int out_size)
{
    const float* sampled_xyz = (const float*)d_in[0];
    const float* point_xyz   = (const float*)d_in[1];
    const float* values      = (const float*)d_in[2];
    const int*   sampled_idx = (const int*)d_in[3];
    const int*   point_feats = (const int*)d_in[4];
    float*       out         = (float*)d_out;

    k_convert<<<4096, 256>>>(values);

    sve_trilerp_kernel<<<(P_TOTAL * 4) / NTHREADS, NTHREADS>>>(
        sampled_xyz, point_xyz, sampled_idx, point_feats, out);
}